// round 2
// baseline (speedup 1.0000x reference)
#include <cuda_runtime.h>
#include <cstdint>

// Problem constants (B=4, S=1024, K=32, V=32000)
#define BB 4
#define SS 1024
#define KK 32
#define VV 32000
#define ROWS (BB * SS)          // 4096
#define ROW_F4 (VV / 4)         // 8000 float4 per row

// ---------------------------------------------------------------------------
// Fused kernel: one block per (b,s) row.
//   - warp 0 computes the 32 softmax probs (live subgraph of the reference:
//     label_counts -> fc2 -> tempe ; log feats -> fc1 -> noise_logit ;
//     probs = softmax(-dists*tempe + noise))
//   - all 8 warps zero the row's 32000 floats (float4 stores)
//   - __syncthreads() orders zero-stores before the scatter
//   - warp 0 scatter-adds the 32 probs (atomicAdd handles duplicate indices)
// The tiny compute is latency-hidden under the write-bandwidth-bound zeroing.
// ---------------------------------------------------------------------------
__global__ void __launch_bounds__(256) fused_combiner_kernel(
    const int*   __restrict__ tgt,
    const float* __restrict__ dists,
    const float* __restrict__ kkf,
    const float* __restrict__ nsp,
    const float* __restrict__ fc1_w1,  // (2,4)
    const float* __restrict__ fc1_b1,  // (4)
    const float* __restrict__ fc1_w2,  // (4,1)
    const float* __restrict__ fc1_b2,  // (1)
    const float* __restrict__ fc2_w1,  // (64,32)
    const float* __restrict__ fc2_b1,  // (32)
    const float* __restrict__ fc2_w2,  // (32,2)
    const float* __restrict__ fc2_b2,  // (2)
    float*       __restrict__ out)     // (ROWS, VV)
{
    const unsigned FULL = 0xffffffffu;
    const int row  = blockIdx.x;
    const int tid  = threadIdx.x;
    const int lane = tid & 31;
    const int wid  = tid >> 5;

    float p = 0.f;
    int   t = 0;

    if (wid == 0) {
        // ---- per-row combiner math (warp 0 only) --------------------------
        int   base = row * KK + lane;
        t          = tgt[base];
        float d    = dists[base];
        float lkf  = logf(kkf[base]);
        float lsp  = logf(nsp[base]);

        // label_counts: distinct nonzero labels in prefix [0..lane]
        int fo = (t != 0) ? 1 : 0;
        #pragma unroll
        for (int j = 0; j < 31; j++) {
            int tj = __shfl_sync(FULL, t, j);
            if (j < lane && tj == t) fo = 0;
        }
        float lc = (float)fo;
        #pragma unroll
        for (int off = 1; off < 32; off <<= 1) {
            float v = __shfl_up_sync(FULL, lc, off);
            if (lane >= off) lc += v;
        }

        // fc1: noise_logit
        float noise = fc1_b2[0];
        #pragma unroll
        for (int m = 0; m < 4; m++) {
            float h = fmaf(lkf, fc1_w1[m], fmaf(lsp, fc1_w1[4 + m], fc1_b1[m]));
            noise = fmaf(tanhf(h), fc1_w2[m], noise);
        }

        // fc2: hidden[lane] = b1[lane] + sum_j feat[j]*W1[j][lane]
        float hid = fc2_b1[lane];
        #pragma unroll
        for (int j = 0; j < 32; j++) {
            float fj = __shfl_sync(FULL, d, j);
            hid = fmaf(fj, fc2_w1[j * 32 + lane], hid);
        }
        #pragma unroll
        for (int j = 0; j < 32; j++) {
            float fj = __shfl_sync(FULL, lc, j);
            hid = fmaf(fj, fc2_w1[(32 + j) * 32 + lane], hid);
        }
        float ht = tanhf(hid);

        // lambda_logit[1] -> tempe
        float l1 = ht * fc2_w2[lane * 2 + 1];
        #pragma unroll
        for (int off = 16; off; off >>= 1) l1 += __shfl_xor_sync(FULL, l1, off);
        l1 += fc2_b2[1];
        float tempe = 1.f / (1.f + expf(-l1));

        // softmax over K of (-d*tempe + noise)
        float logit = fmaf(-d, tempe, noise);
        float mx = logit;
        #pragma unroll
        for (int off = 16; off; off >>= 1) mx = fmaxf(mx, __shfl_xor_sync(FULL, mx, off));
        float e = expf(logit - mx);
        float s = e;
        #pragma unroll
        for (int off = 16; off; off >>= 1) s += __shfl_xor_sync(FULL, s, off);
        p = e / s;
    }

    // ---- zero the row (all 256 threads, float4 stores) --------------------
    float4* rowp = (float4*)(out + (size_t)row * VV);
    const float4 z = make_float4(0.f, 0.f, 0.f, 0.f);
    #pragma unroll 4
    for (int i = tid; i < ROW_F4; i += 256) rowp[i] = z;

    __syncthreads();  // orders zero-stores before the scatter (block scope)

    // ---- scatter-add (warp 0) --------------------------------------------
    if (wid == 0) {
        atomicAdd(out + (size_t)row * VV + t, p);
    }
}

// metadata order:
//  0 tgt_index(i32) 1 knn_dists 2 knn_key_feature 3 network_probs(UNUSED)
//  4 network_select_probs 5 dfc_w(UNUSED) 6 dfc_b(UNUSED)
//  7 fc1_w1 8 fc1_b1 9 fc1_w2 10 fc1_b2 11 fc2_w1 12 fc2_b1 13 fc2_w2 14 fc2_b2
extern "C" void kernel_launch(void* const* d_in, const int* in_sizes, int n_in,
                              void* d_out, int out_size) {
    const int*   tgt    = (const int*)  d_in[0];
    const float* dists  = (const float*)d_in[1];
    const float* kkf    = (const float*)d_in[2];
    const float* nsp    = (const float*)d_in[4];
    const float* fc1_w1 = (const float*)d_in[7];
    const float* fc1_b1 = (const float*)d_in[8];
    const float* fc1_w2 = (const float*)d_in[9];
    const float* fc1_b2 = (const float*)d_in[10];
    const float* fc2_w1 = (const float*)d_in[11];
    const float* fc2_b1 = (const float*)d_in[12];
    const float* fc2_w2 = (const float*)d_in[13];
    const float* fc2_b2 = (const float*)d_in[14];
    float* out = (float*)d_out;

    fused_combiner_kernel<<<ROWS, 256>>>(tgt, dists, kkf, nsp,
                                         fc1_w1, fc1_b1, fc1_w2, fc1_b2,
                                         fc2_w1, fc2_b1, fc2_w2, fc2_b2,
                                         out);
}

// round 3
// speedup vs baseline: 1.0162x; 1.0162x over previous
#include <cuda_runtime.h>
#include <cstdint>

// Problem constants (B=4, S=1024, K=32, V=32000)
#define BB 4
#define SS 1024
#define KK 32
#define VV 32000
#define ROWS (BB * SS)          // 4096
#define ROW_F4 (VV / 4)         // 8000 float4 per row

// Scratch for the per-row probs (512 KB, device global — no allocation).
__device__ float g_probs[ROWS * KK];

__device__ __forceinline__ float fast_tanh(float x) {
    float r;
    asm("tanh.approx.f32 %0, %1;" : "=f"(r) : "f"(x));
    return r;
}

// ---------------------------------------------------------------------------
// Kernel 1: one block per row. Warps 1..7 (224 threads) zero the row's 32000
// floats; warp 0 concurrently computes probs and writes them to g_probs.
// No barrier — the two jobs are independent. Scatter happens in kernel 2
// (stream order guarantees zeroing completed).
// ---------------------------------------------------------------------------
__global__ void __launch_bounds__(256) zero_and_compute_kernel(
    const int*   __restrict__ tgt,
    const float* __restrict__ dists,
    const float* __restrict__ kkf,
    const float* __restrict__ nsp,
    const float* __restrict__ fc1_w1,  // (2,4)
    const float* __restrict__ fc1_b1,  // (4)
    const float* __restrict__ fc1_w2,  // (4,1)
    const float* __restrict__ fc1_b2,  // (1)
    const float* __restrict__ fc2_w1,  // (64,32)
    const float* __restrict__ fc2_b1,  // (32)
    const float* __restrict__ fc2_w2,  // (32,2)
    const float* __restrict__ fc2_b2,  // (2)
    float*       __restrict__ out)     // (ROWS, VV)
{
    const unsigned FULL = 0xffffffffu;
    const int row  = blockIdx.x;
    const int tid  = threadIdx.x;
    const int lane = tid & 31;

    if (tid >= 32) {
        // ---- zero the row: 224 threads, float4 stores ---------------------
        float4* rowp = (float4*)(out + (size_t)row * VV);
        const float4 z = make_float4(0.f, 0.f, 0.f, 0.f);
        for (int i = tid - 32; i < ROW_F4; i += 224) rowp[i] = z;
        return;
    }

    // ---- warp 0: per-row combiner math -----------------------------------
    int   base = row * KK + lane;
    int   t    = tgt[base];
    float d    = dists[base];
    float lkf  = __logf(kkf[base]);
    float lsp  = __logf(nsp[base]);

    // label_counts: distinct nonzero labels in prefix [0..lane]
    int fo = (t != 0) ? 1 : 0;
    #pragma unroll
    for (int j = 0; j < 31; j++) {
        int tj = __shfl_sync(FULL, t, j);
        if (j < lane && tj == t) fo = 0;
    }
    float lc = (float)fo;
    #pragma unroll
    for (int off = 1; off < 32; off <<= 1) {
        float v = __shfl_up_sync(FULL, lc, off);
        if (lane >= off) lc += v;
    }

    // fc1: noise_logit = tanh([lkf,lsp] @ W1 + b1) @ W2 + b2
    float noise = fc1_b2[0];
    #pragma unroll
    for (int m = 0; m < 4; m++) {
        float h = fmaf(lkf, fc1_w1[m], fmaf(lsp, fc1_w1[4 + m], fc1_b1[m]));
        noise = fmaf(fast_tanh(h), fc1_w2[m], noise);
    }

    // fc2: hidden[lane] = b1[lane] + sum_j feat[j]*W1[j][lane]
    float hid = fc2_b1[lane];
    #pragma unroll
    for (int j = 0; j < 32; j++) {
        float fj = __shfl_sync(FULL, d, j);
        hid = fmaf(fj, fc2_w1[j * 32 + lane], hid);
    }
    #pragma unroll
    for (int j = 0; j < 32; j++) {
        float fj = __shfl_sync(FULL, lc, j);
        hid = fmaf(fj, fc2_w1[(32 + j) * 32 + lane], hid);
    }
    float ht = fast_tanh(hid);

    // lambda_logit[1] -> tempe
    float l1 = ht * fc2_w2[lane * 2 + 1];
    #pragma unroll
    for (int off = 16; off; off >>= 1) l1 += __shfl_xor_sync(FULL, l1, off);
    l1 += fc2_b2[1];
    float tempe = 1.f / (1.f + __expf(-l1));

    // softmax over K of (-d*tempe + noise)
    float logit = fmaf(-d, tempe, noise);
    float mx = logit;
    #pragma unroll
    for (int off = 16; off; off >>= 1) mx = fmaxf(mx, __shfl_xor_sync(FULL, mx, off));
    float e = __expf(logit - mx);
    float s = e;
    #pragma unroll
    for (int off = 16; off; off >>= 1) s += __shfl_xor_sync(FULL, s, off);
    g_probs[base] = e / s;
}

// ---------------------------------------------------------------------------
// Kernel 2: scatter the precomputed probs. One warp per row.
// Runs after kernel 1 (stream order), so all rows are zeroed.
// ---------------------------------------------------------------------------
__global__ void __launch_bounds__(256) scatter_kernel(
    const int* __restrict__ tgt,
    float*     __restrict__ out)
{
    int gwarp = (blockIdx.x * blockDim.x + threadIdx.x) >> 5;
    int lane  = threadIdx.x & 31;
    if (gwarp >= ROWS) return;
    int base = gwarp * KK + lane;
    atomicAdd(out + (size_t)gwarp * VV + tgt[base], g_probs[base]);
}

// metadata order:
//  0 tgt_index(i32) 1 knn_dists 2 knn_key_feature 3 network_probs(UNUSED)
//  4 network_select_probs 5 dfc_w(UNUSED) 6 dfc_b(UNUSED)
//  7 fc1_w1 8 fc1_b1 9 fc1_w2 10 fc1_b2 11 fc2_w1 12 fc2_b1 13 fc2_w2 14 fc2_b2
extern "C" void kernel_launch(void* const* d_in, const int* in_sizes, int n_in,
                              void* d_out, int out_size) {
    const int*   tgt    = (const int*)  d_in[0];
    const float* dists  = (const float*)d_in[1];
    const float* kkf    = (const float*)d_in[2];
    const float* nsp    = (const float*)d_in[4];
    const float* fc1_w1 = (const float*)d_in[7];
    const float* fc1_b1 = (const float*)d_in[8];
    const float* fc1_w2 = (const float*)d_in[9];
    const float* fc1_b2 = (const float*)d_in[10];
    const float* fc2_w1 = (const float*)d_in[11];
    const float* fc2_b1 = (const float*)d_in[12];
    const float* fc2_w2 = (const float*)d_in[13];
    const float* fc2_b2 = (const float*)d_in[14];
    float* out = (float*)d_out;

    zero_and_compute_kernel<<<ROWS, 256>>>(tgt, dists, kkf, nsp,
                                           fc1_w1, fc1_b1, fc1_w2, fc1_b2,
                                           fc2_w1, fc2_b1, fc2_w2, fc2_b2,
                                           out);

    // 4096 warps, 8 warps/block -> 512 blocks
    scatter_kernel<<<ROWS / 8, 256>>>(tgt, out);
}

// round 4
// speedup vs baseline: 1.0600x; 1.0431x over previous
#include <cuda_runtime.h>
#include <cstdint>

// Problem constants (B=4, S=1024, K=32, V=32000)
#define BB 4
#define SS 1024
#define KK 32
#define VV 32000
#define ROWS (BB * SS)          // 4096
#define CHUNK 1024              // floats per zero-block (256 threads * float4)
#define NCHUNK ((VV + CHUNK - 1) / CHUNK)   // 32 (last chunk = 256 floats)

// Scratch (device globals — no allocation). Dedup-combined per-row scatter list.
__device__ float g_probs[ROWS * KK];
__device__ int   g_tgt  [ROWS * KK];

__device__ __forceinline__ float fast_tanh(float x) {
    float r;
    asm("tanh.approx.f32 %0, %1;" : "=f"(r) : "f"(x));
    return r;
}

// ---------------------------------------------------------------------------
// Kernel A: one warp per (b,s) row. Computes the 32 softmax probs (live
// subgraph only), then combines duplicate targets in-warp: lane keeps its
// target only if it is the first occurrence, with p = sum over duplicates.
// Dropped lanes store t = -1. Result goes to g_tgt/g_probs.
// ---------------------------------------------------------------------------
__global__ void __launch_bounds__(256) compute_kernel(
    const int*   __restrict__ tgt,
    const float* __restrict__ dists,
    const float* __restrict__ kkf,
    const float* __restrict__ nsp,
    const float* __restrict__ fc1_w1,  // (2,4)
    const float* __restrict__ fc1_b1,  // (4)
    const float* __restrict__ fc1_w2,  // (4,1)
    const float* __restrict__ fc1_b2,  // (1)
    const float* __restrict__ fc2_w1,  // (64,32)
    const float* __restrict__ fc2_b1,  // (32)
    const float* __restrict__ fc2_w2,  // (32,2)
    const float* __restrict__ fc2_b2)  // (2)
{
    const unsigned FULL = 0xffffffffu;
    int gwarp = (blockIdx.x * blockDim.x + threadIdx.x) >> 5;
    int lane  = threadIdx.x & 31;
    if (gwarp >= ROWS) return;

    int   base = gwarp * KK + lane;
    int   t    = tgt[base];
    float d    = dists[base];
    float lkf  = __logf(kkf[base]);
    float lsp  = __logf(nsp[base]);

    // label_counts: distinct nonzero labels in prefix [0..lane]
    int fo = (t != 0) ? 1 : 0;
    #pragma unroll
    for (int j = 0; j < 31; j++) {
        int tj = __shfl_sync(FULL, t, j);
        if (j < lane && tj == t) fo = 0;
    }
    float lc = (float)fo;
    #pragma unroll
    for (int off = 1; off < 32; off <<= 1) {
        float v = __shfl_up_sync(FULL, lc, off);
        if (lane >= off) lc += v;
    }

    // fc1 -> noise_logit
    float noise = fc1_b2[0];
    #pragma unroll
    for (int m = 0; m < 4; m++) {
        float h = fmaf(lkf, fc1_w1[m], fmaf(lsp, fc1_w1[4 + m], fc1_b1[m]));
        noise = fmaf(fast_tanh(h), fc1_w2[m], noise);
    }

    // fc2: hidden[lane]
    float hid = fc2_b1[lane];
    #pragma unroll
    for (int j = 0; j < 32; j++) {
        float fj = __shfl_sync(FULL, d, j);
        hid = fmaf(fj, fc2_w1[j * 32 + lane], hid);
    }
    #pragma unroll
    for (int j = 0; j < 32; j++) {
        float fj = __shfl_sync(FULL, lc, j);
        hid = fmaf(fj, fc2_w1[(32 + j) * 32 + lane], hid);
    }
    float ht = fast_tanh(hid);

    // lambda_logit[1] -> tempe
    float l1 = ht * fc2_w2[lane * 2 + 1];
    #pragma unroll
    for (int off = 16; off; off >>= 1) l1 += __shfl_xor_sync(FULL, l1, off);
    l1 += fc2_b2[1];
    float tempe = 1.f / (1.f + __expf(-l1));

    // softmax over K of (-d*tempe + noise)
    float logit = fmaf(-d, tempe, noise);
    float mx = logit;
    #pragma unroll
    for (int off = 16; off; off >>= 1) mx = fmaxf(mx, __shfl_xor_sync(FULL, mx, off));
    float e = __expf(logit - mx);
    float s = e;
    #pragma unroll
    for (int off = 16; off; off >>= 1) s += __shfl_xor_sync(FULL, s, off);
    float p = e / s;

    // ---- in-warp duplicate-target combine ---------------------------------
    float psum = 0.f;
    int firstl = 32;
    #pragma unroll
    for (int j = 0; j < 32; j++) {
        int   tj = __shfl_sync(FULL, t, j);
        float pj = __shfl_sync(FULL, p, j);
        if (tj == t) { psum += pj; firstl = min(firstl, j); }
    }
    bool keep = (firstl == lane);
    g_tgt[base]   = keep ? t : -1;
    g_probs[base] = psum;
}

// ---------------------------------------------------------------------------
// Kernel B: zero + inline scatter. One block per 1024-float chunk of one row
// (flat write shape: 1 float4 store per thread — the known-good BW pattern).
// After the zero stores, warp 0 writes any of the row's (deduped) targets
// that fall inside this chunk (plain STG; the zero of that address was done
// by this same block, ordered by __syncthreads).
// ---------------------------------------------------------------------------
__global__ void __launch_bounds__(256) zero_scatter_kernel(
    float* __restrict__ out)
{
    const int row   = blockIdx.y;
    const int chunk = blockIdx.x;
    const int tid   = threadIdx.x;

    const int lo = chunk * CHUNK;
    const int n  = min(CHUNK, VV - lo);          // 1024, or 256 for last chunk
    float* rowp = out + (size_t)row * VV + lo;

    // prefetch the scatter list (warp 0) before the stores
    int   t = -1;
    float p = 0.f;
    if (tid < 32) {
        t = g_tgt[row * KK + tid];
        p = g_probs[row * KK + tid];
    }

    // zero this chunk: one float4 per thread
    int i4 = tid * 4;
    if (i4 < n) *(float4*)(rowp + i4) = make_float4(0.f, 0.f, 0.f, 0.f);

    __syncthreads();  // order zero-stores before the targeted stores

    if (tid < 32) {
        int loc = t - lo;
        if (loc >= 0 && loc < n) rowp[loc] = p;   // t == -1 never matches
    }
}

// metadata order:
//  0 tgt_index(i32) 1 knn_dists 2 knn_key_feature 3 network_probs(UNUSED)
//  4 network_select_probs 5 dfc_w(UNUSED) 6 dfc_b(UNUSED)
//  7 fc1_w1 8 fc1_b1 9 fc1_w2 10 fc1_b2 11 fc2_w1 12 fc2_b1 13 fc2_w2 14 fc2_b2
extern "C" void kernel_launch(void* const* d_in, const int* in_sizes, int n_in,
                              void* d_out, int out_size) {
    const int*   tgt    = (const int*)  d_in[0];
    const float* dists  = (const float*)d_in[1];
    const float* kkf    = (const float*)d_in[2];
    const float* nsp    = (const float*)d_in[4];
    const float* fc1_w1 = (const float*)d_in[7];
    const float* fc1_b1 = (const float*)d_in[8];
    const float* fc1_w2 = (const float*)d_in[9];
    const float* fc1_b2 = (const float*)d_in[10];
    const float* fc2_w1 = (const float*)d_in[11];
    const float* fc2_b1 = (const float*)d_in[12];
    const float* fc2_w2 = (const float*)d_in[13];
    const float* fc2_b2 = (const float*)d_in[14];
    float* out = (float*)d_out;

    // A: 4096 warps, 8 warps/block -> 512 blocks
    compute_kernel<<<ROWS / 8, 256>>>(tgt, dists, kkf, nsp,
                                      fc1_w1, fc1_b1, fc1_w2, fc1_b2,
                                      fc2_w1, fc2_b1, fc2_w2, fc2_b2);

    // B: flat zero+scatter, grid (32 chunks, 4096 rows)
    dim3 grid(NCHUNK, ROWS);
    zero_scatter_kernel<<<grid, 256>>>(out);
}